// round 16
// baseline (speedup 1.0000x reference)
#include <cuda_runtime.h>
#include <cstdint>

// ---------------------------------------------------------------------------
// CharacterEmbeddingLayer via vocabulary factorization + split head.
//  - conv: PP table, padded 71-u64 char rows baked into g_pp (odd stride ->
//    full bank-pair coverage), chunks bulk-copied with cp.async.bulk.
//  - proj: x-panel resident (bulk-copied), weights streamed (R12).
//  - hwy: channel-split resident weights, 16 tokens/thread (R15).
// NOTE: tcgen05 unavailable (harness targets compute_103 virtual arch).
// ---------------------------------------------------------------------------

#define NTOK  25600      // 64*400 tokens

typedef unsigned long long u64;

// PP table, padded: [13 chunks][96 chars][71 u64]  (14 pieces x 5 u64 + 1 pad)
__device__ __align__(128) float g_pp[13 * 96 * 142];
// conv outputs: [NTOK][400]
__device__ __align__(128) float g_outs[(size_t)NTOK * 400];
// head intermediates: [NTOK][128]
__device__ __align__(128) float g_x1[(size_t)NTOK * 128];
__device__ __align__(128) float g_x2[(size_t)NTOK * 128];

// ---------------- packed fp32x2 + async helpers -----------------------------
__device__ __forceinline__ void ffma2(u64 &acc, u64 a, u64 b) {
    asm("fma.rn.f32x2 %0, %1, %2, %0;" : "+l"(acc) : "l"(a), "l"(b));
}
__device__ __forceinline__ u64 fadd2(u64 a, u64 b) {
    u64 r; asm("add.rn.f32x2 %0, %1, %2;" : "=l"(r) : "l"(a), "l"(b)); return r;
}
__device__ __forceinline__ void unpack2(u64 v, float &lo, float &hi) {
    asm("mov.b64 {%0, %1}, %2;" : "=f"(lo), "=f"(hi) : "l"(v));
}
__device__ __forceinline__ float hadd2(u64 v) {
    float lo, hi; unpack2(v, lo, hi); return lo + hi;
}
__device__ __forceinline__ float tanh_fast(float x) {
    float y;
    asm("tanh.approx.f32 %0, %1;" : "=f"(y) : "f"(x));
    return y;
}
__device__ __forceinline__ uint32_t smem_u32(const void* p) {
    return (uint32_t)__cvta_generic_to_shared(p);
}
__device__ __forceinline__ void cp16(uint32_t dst, const void* src) {
    asm volatile("cp.async.ca.shared.global [%0], [%1], 16;" :: "r"(dst), "l"(src));
}
__device__ __forceinline__ void cp_commit() {
    asm volatile("cp.async.commit_group;");
}
template<int N> __device__ __forceinline__ void cp_wait() {
    asm volatile("cp.async.wait_group %0;" :: "n"(N));
}
// ---- bulk-copy (UBLKCP) + mbarrier ----------------------------------------
__device__ __forceinline__ void mbar_init(uint32_t mbar, uint32_t cnt) {
    asm volatile("mbarrier.init.shared.b64 [%0], %1;" :: "r"(mbar), "r"(cnt) : "memory");
}
__device__ __forceinline__ void mbar_expect(uint32_t mbar, uint32_t tx) {
    asm volatile("mbarrier.arrive.expect_tx.shared.b64 _, [%0], %1;"
                 :: "r"(mbar), "r"(tx) : "memory");
}
__device__ __forceinline__ void bulk_g2s(uint32_t dst, const void* src,
                                         uint32_t bytes, uint32_t mbar) {
    asm volatile(
        "cp.async.bulk.shared::cluster.global.mbarrier::complete_tx::bytes "
        "[%0], [%1], %2, [%3];"
        :: "r"(dst), "l"(src), "r"(bytes), "r"(mbar) : "memory");
}
__device__ __forceinline__ void mbar_wait(uint32_t mbar, uint32_t parity) {
    asm volatile(
        "{\n\t.reg .pred P;\n"
        "WL_%=:\n\t"
        "mbarrier.try_wait.parity.acquire.cta.shared::cta.b64 P, [%0], %1, 0x989680;\n\t"
        "@P bra.uni WD_%=;\n\t"
        "bra.uni WL_%=;\n\t"
        "WD_%=:\n\t}"
        :: "r"(mbar), "r"(parity) : "memory");
}

// ---------------------------------------------------------------------------
// Kernel A: precompute PP (padded 71-u64 rows).  grid = (96, 14), 128 thr.
// ---------------------------------------------------------------------------
__global__ void pp_kernel(const float* __restrict__ cv,
                          const float* __restrict__ f2, const float* __restrict__ f3,
                          const float* __restrict__ f4, const float* __restrict__ f5)
{
    __shared__ float scv[64];
    const int c  = blockIdx.x;
    const int pg = blockIdx.y;
    const int j  = threadIdx.x;
    if (j < 64) scv[j] = __ldg(cv + c * 64 + j);
    __syncthreads();

    if (j < 104) {
        float s = 0.0f;
        if (j < 100) {
            const float* fp; int pl, RL;
            if (pg < 2)      { fp = f2; pl = pg;     RL = 2; }
            else if (pg < 5) { fp = f3; pl = pg - 2; RL = 3; }
            else if (pg < 9) { fp = f4; pl = pg - 5; RL = 4; }
            else             { fp = f5; pl = pg - 9; RL = 5; }
            const float4* fr = reinterpret_cast<const float4*>(fp + (j * RL + pl) * 64);
            #pragma unroll 4
            for (int q = 0; q < 16; q++) {
                const float4 fv = __ldg(fr + q);
                s += scv[4*q]   * fv.x + scv[4*q+1] * fv.y
                   + scv[4*q+2] * fv.z + scv[4*q+3] * fv.w;
            }
        }
        // padded layout: chunk (j>>3) stride 96*142 floats; char row 142 floats
        g_pp[(j >> 3) * (96 * 142) + c * 142 + pg * 10 + (j & 7)] = s;
    }
}

// ---------------------------------------------------------------------------
// Kernel B: conv as table sums.  grid = 400 (64 tok/CTA), 256 threads,
// 2 CTAs/SM; chunks bulk-copied, double-buffered.  Char row stride 71 u64:
// 7*idx mod 16 covers all bank-pair residues -> conflict mitigation.
// ---------------------------------------------------------------------------
#define TB1  256
#define CSTRIDE     71                     // u64 per char row
#define CHUNK_U64   (96 * CSTRIDE)         // 6816
#define CHUNK_BYTES (CHUNK_U64 * 8)        // 54528
#define SMEMB_BYTES (2 * CHUNK_BYTES)      // 109056 B

template<int W, int PB, int BOFF>
__device__ __forceinline__ void branch_sum(const u64* __restrict__ s_pp,
                                           const int (&bix)[16],
                                           float* __restrict__ orow,
                                           int g, int j2)
{
    constexpr int L = 17 - W;
    float m0 = -1e30f, m1 = -1e30f;
    #pragma unroll
    for (int l = 0; l < L; l++) {
        u64 a = s_pp[bix[l] + PB * 5];
        #pragma unroll
        for (int p = 1; p < W; p++)
            a = fadd2(a, s_pp[bix[l + p] + (PB + p) * 5]);
        float lo, hi; unpack2(a, lo, hi);
        m0 = fmaxf(m0, lo);
        m1 = fmaxf(m1, hi);
    }
    if (g < 12 || j2 < 2) {     // chunk 12: only filters 96..99 are real
        float2 r;
        r.x = tanh_fast(m0);
        r.y = tanh_fast(m1);
        *reinterpret_cast<float2*>(orow + BOFF + g * 8 + j2 * 2) = r;
    }
}

__global__ void __launch_bounds__(TB1, 2)
conv_sum_kernel(const int* __restrict__ idxs)
{
    extern __shared__ u64 s_pp2[];
    __shared__ __align__(8) u64 mb[2];
    u64* buf[2] = { s_pp2, s_pp2 + CHUNK_U64 };
    const uint32_t sb[2] = { smem_u32(buf[0]), smem_u32(buf[1]) };
    const uint32_t mbu[2] = { smem_u32(&mb[0]), smem_u32(&mb[1]) };

    const int tid = threadIdx.x;
    const int j2  = tid & 3;
    const int token = blockIdx.x * 64 + (tid >> 2);

    int bix[16];
    {
        const int4* ip4 = reinterpret_cast<const int4*>(idxs + token * 16);
        const int4 A = __ldg(ip4 + 0), B = __ldg(ip4 + 1);
        const int4 C = __ldg(ip4 + 2), D = __ldg(ip4 + 3);
        bix[ 0] = A.x * CSTRIDE + j2; bix[ 1] = A.y * CSTRIDE + j2;
        bix[ 2] = A.z * CSTRIDE + j2; bix[ 3] = A.w * CSTRIDE + j2;
        bix[ 4] = B.x * CSTRIDE + j2; bix[ 5] = B.y * CSTRIDE + j2;
        bix[ 6] = B.z * CSTRIDE + j2; bix[ 7] = B.w * CSTRIDE + j2;
        bix[ 8] = C.x * CSTRIDE + j2; bix[ 9] = C.y * CSTRIDE + j2;
        bix[10] = C.z * CSTRIDE + j2; bix[11] = C.w * CSTRIDE + j2;
        bix[12] = D.x * CSTRIDE + j2; bix[13] = D.y * CSTRIDE + j2;
        bix[14] = D.z * CSTRIDE + j2; bix[15] = D.w * CSTRIDE + j2;
    }

    float* orow = g_outs + (size_t)token * 400;

    if (tid == 0) { mbar_init(mbu[0], 1); mbar_init(mbu[1], 1); }
    __syncthreads();

    if (tid == 0) {
        mbar_expect(mbu[0], CHUNK_BYTES);
        bulk_g2s(sb[0], g_pp, CHUNK_BYTES, mbu[0]);
    }

    int ph0 = 0, ph1 = 0;
    #pragma unroll 1
    for (int g = 0; g < 13; g++) {
        if (g < 12 && tid == 0) {
            const int b = (g + 1) & 1;
            mbar_expect(mbu[b], CHUNK_BYTES);
            bulk_g2s(sb[b], g_pp + (g + 1) * (96 * 142), CHUNK_BYTES, mbu[b]);
        }
        if (g & 1) { mbar_wait(mbu[1], ph1); ph1 ^= 1; }
        else       { mbar_wait(mbu[0], ph0); ph0 ^= 1; }

        const u64* sp = buf[g & 1];
        branch_sum<2, 0,   0>(sp, bix, orow, g, j2);
        branch_sum<3, 2, 100>(sp, bix, orow, g, j2);
        branch_sum<4, 5, 200>(sp, bix, orow, g, j2);
        branch_sum<5, 9, 300>(sp, bix, orow, g, j2);
        __syncthreads();
    }
}

// ---------------------------------------------------------------------------
// Kernel C1: projection (R12 exact).  grid 400 (64 tok/CTA), 512 threads,
// 1 CTA/SM.  x panel bulk-copied once; w_proj streamed (cp16, pitch 44).
// ---------------------------------------------------------------------------
#define PJ_XROW 400
#define PJ_XF   (64 * PJ_XROW)             // 25600 floats
#define PJ_WP   44
#define PJ_WF   (128 * PJ_WP)              // 5632 floats per buffer
#define PJ_SMEM ((PJ_XF + 2 * PJ_WF) * 4)  // 147456 B

__global__ void __launch_bounds__(512, 1)
proj_kernel(const float* __restrict__ wp, float* __restrict__ xout)
{
    extern __shared__ float sm[];
    __shared__ __align__(8) u64 pmb;
    float* s_x = sm;                       // [64][400]
    float* w0  = s_x + PJ_XF;              // [128][44]
    float* w1  = w0 + PJ_WF;
    const uint32_t xb  = smem_u32(s_x);
    const uint32_t wb[2] = { smem_u32(w0), smem_u32(w1) };
    const uint32_t pmbu = smem_u32(&pmb);
    float* const wf[2] = { w0, w1 };

    const int tid  = threadIdx.x;
    const int c2   = tid & 63;
    const int tq   = tid >> 6;
    const int tok0 = blockIdx.x * 64;

    if (tid == 0) mbar_init(pmbu, 1);
    __syncthreads();
    if (tid == 0) {
        mbar_expect(pmbu, PJ_XF * 4);
        bulk_g2s(xb, g_outs + (size_t)tok0 * 400, PJ_XF * 4, pmbu);
    }

    auto stage_w = [&](int kc, uint32_t b) {
        #pragma unroll 1
        for (int i = tid; i < 1280; i += 512) {
            const int r = i / 10, q = i - r * 10;
            cp16(b + (uint32_t)(r * PJ_WP + 4 * q) * 4u,
                 wp + r * 400 + kc * 40 + 4 * q);
        }
    };

    stage_w(0, wb[0]);
    cp_commit();

    u64 a0[8], a1[8];
    #pragma unroll
    for (int i = 0; i < 8; i++) { a0[i] = 0ull; a1[i] = 0ull; }

    mbar_wait(pmbu, 0);

    #pragma unroll 1
    for (int kc = 0; kc < 10; kc++) {
        if (kc < 9) { stage_w(kc + 1, wb[(kc + 1) & 1]); cp_commit(); cp_wait<1>(); }
        else        { cp_wait<0>(); }
        __syncthreads();
        const float* b = wf[kc & 1];
        #pragma unroll
        for (int q = 0; q < 10; q++) {
            const ulonglong2 wa = *reinterpret_cast<const ulonglong2*>(b + c2 * PJ_WP + 4 * q);
            const ulonglong2 wv = *reinterpret_cast<const ulonglong2*>(b + (c2 + 64) * PJ_WP + 4 * q);
            #pragma unroll
            for (int i = 0; i < 8; i++) {
                const ulonglong2 xv = *reinterpret_cast<const ulonglong2*>(
                    s_x + (tq * 8 + i) * PJ_XROW + kc * 40 + 4 * q);
                ffma2(a0[i], xv.x, wa.x); ffma2(a0[i], xv.y, wa.y);
                ffma2(a1[i], xv.x, wv.x); ffma2(a1[i], xv.y, wv.y);
            }
        }
        __syncthreads();
    }

    #pragma unroll
    for (int i = 0; i < 8; i++) {
        const int t = tok0 + tq * 8 + i;
        xout[(size_t)t * 128 + c2]      = hadd2(a0[i]);
        xout[(size_t)t * 128 + c2 + 64] = hadd2(a1[i]);
    }
}

// ---------------------------------------------------------------------------
// Kernel C2: one highway layer (R15 exact).  grid (148, 2), 256 threads,
// 2 CTAs/SM; channel-split resident weights; 16 tokens/thread.
// ---------------------------------------------------------------------------
#define HW_WF   (2 * 256 * 32)             // 16384 floats (65536 B)
#define HW_XU   33                         // float4 units per token row
#define HW_XF   (64 * HW_XU * 4)           // 8448 floats
#define HW_SMEM ((HW_WF + HW_XF) * 4)      // 99328 B

__global__ void __launch_bounds__(256, 2)
hwy_kernel(const float* __restrict__ tw, const float* __restrict__ tb,
           const float* __restrict__ gw, const float* __restrict__ gb,
           const float* __restrict__ xin, float* __restrict__ xout)
{
    extern __shared__ float sm[];
    float* sw = sm;                        // [2 mats][256 atoms][32 floats]
    float* xp = sw + HW_WF;                // [64][132]
    const uint32_t swb = smem_u32(sw);
    const uint32_t xpb = smem_u32(xp);

    const int tid = threadIdx.x;
    const int c   = tid & 63;
    const int tg  = tid >> 6;              // token group 0..3 (16 tokens each)
    const int h   = blockIdx.y;
    const int ch  = h * 64 + c;

    const float tbv = __ldg(tb + ch);
    const float gbv = __ldg(gb + ch);

    #pragma unroll 1
    for (int i = tid; i < 4096; i += 256) {
        const int m  = i >> 11;
        const int r  = (i >> 3) & 255;
        const int q  = i & 7;
        const int cc = r & 63;
        const int s  = r >> 6;
        const int dst = m * 2048 + r * 8 + (q ^ (cc & 7));
        const float* src = (m ? gw : tw) + (h * 64 + cc) * 128 + s * 32 + q * 4;
        cp16(swb + (uint32_t)dst * 16u, src);
    }
    cp_commit();

    const int qx = c & 7;

    #pragma unroll 1
    for (int b = blockIdx.x; b < 400; b += 148) {
        const int tok0 = b * 64;
        #pragma unroll 1
        for (int i = tid; i < 2048; i += 256) {
            const int t = i >> 5, u = i & 31;
            cp16(xpb + (uint32_t)(t * HW_XU + u) * 16u,
                 xin + (size_t)(tok0 + t) * 128 + u * 4);
        }
        cp_commit();
        cp_wait<0>();
        __syncthreads();

        u64 at[16], ag[16];
        #pragma unroll
        for (int i = 0; i < 16; i++) { at[i] = 0ull; ag[i] = 0ull; }

        #pragma unroll 1
        for (int s = 0; s < 4; s++) {
            #pragma unroll
            for (int q = 0; q < 8; q++) {
                const int qq = q ^ qx;
                const ulonglong2 wt = *reinterpret_cast<const ulonglong2*>(
                    sw + ((s * 64 + c) * 8 + qq) * 4);
                const ulonglong2 wg = *reinterpret_cast<const ulonglong2*>(
                    sw + 8192 + ((s * 64 + c) * 8 + qq) * 4);
                #pragma unroll
                for (int i = 0; i < 16; i++) {
                    const ulonglong2 xv = *reinterpret_cast<const ulonglong2*>(
                        xp + ((tg * 16 + i) * HW_XU + s * 8 + q) * 4);
                    ffma2(at[i], xv.x, wt.x); ffma2(at[i], xv.y, wt.y);
                    ffma2(ag[i], xv.x, wg.x); ffma2(ag[i], xv.y, wg.y);
                }
            }
        }

        #pragma unroll
        for (int i = 0; i < 16; i++) {
            const int t = tg * 16 + i;
            const float xo = xp[t * (HW_XU * 4) + ch];
            const float tv = fmaxf(hadd2(at[i]) + tbv, 0.0f);
            const float g  = 0.5f * tanh_fast(0.5f * (hadd2(ag[i]) + gbv)) + 0.5f;
            xout[(size_t)(tok0 + t) * 128 + ch] = g * tv + (1.0f - g) * xo;
        }

        __syncthreads();
    }
}

// ---------------------------------------------------------------------------
extern "C" void kernel_launch(void* const* d_in, const int* in_sizes, int n_in,
                              void* d_out, int out_size)
{
    const int*   idxs = (const int*)  d_in[0];
    const float* cv   = (const float*)d_in[1];
    const float* f2   = (const float*)d_in[2];
    const float* f3   = (const float*)d_in[3];
    const float* f4   = (const float*)d_in[4];
    const float* f5   = (const float*)d_in[5];
    const float* wp   = (const float*)d_in[6];
    const float* tw0  = (const float*)d_in[7];
    const float* tb0  = (const float*)d_in[8];
    const float* tw1  = (const float*)d_in[9];
    const float* tb1  = (const float*)d_in[10];
    const float* gw0  = (const float*)d_in[11];
    const float* gb0  = (const float*)d_in[12];
    const float* gw1  = (const float*)d_in[13];
    const float* gb1  = (const float*)d_in[14];
    float* out = (float*)d_out;

    static bool attr_done = false;
    if (!attr_done) {
        cudaFuncSetAttribute(conv_sum_kernel,
                             cudaFuncAttributeMaxDynamicSharedMemorySize, SMEMB_BYTES);
        cudaFuncSetAttribute(proj_kernel,
                             cudaFuncAttributeMaxDynamicSharedMemorySize, PJ_SMEM);
        cudaFuncSetAttribute(hwy_kernel,
                             cudaFuncAttributeMaxDynamicSharedMemorySize, HW_SMEM);
        attr_done = true;
    }

    float* x1; cudaGetSymbolAddress((void**)&x1, g_x1);
    float* x2; cudaGetSymbolAddress((void**)&x2, g_x2);

    pp_kernel<<<dim3(96, 14), 128>>>(cv, f2, f3, f4, f5);
    conv_sum_kernel<<<NTOK / 64, TB1, SMEMB_BYTES>>>(idxs);
    proj_kernel<<<NTOK / 64, 512, PJ_SMEM>>>(wp, x1);
    hwy_kernel<<<dim3(148, 2), 256, HW_SMEM>>>(tw0, tb0, gw0, gb0, x1, x2);
    hwy_kernel<<<dim3(148, 2), 256, HW_SMEM>>>(tw1, tb1, gw1, gb1, x2, out);
}

// round 17
// speedup vs baseline: 1.0425x; 1.0425x over previous
#include <cuda_runtime.h>
#include <cstdint>

// ---------------------------------------------------------------------------
// CharacterEmbeddingLayer via vocabulary factorization + split head.
//  - conv: PP table (stride-70 rows, R15 exact — stride-71 A/B regressed),
//    chunks bulk-copied with cp.async.bulk + mbarrier.
//  - proj: x-resident / weight-streamed, NEW 16-token blocking (ratio 0.75).
//  - hwy: channel-split resident weights, 16 tokens/thread (R15 exact).
// NOTE: tcgen05 unavailable (harness targets compute_103 virtual arch).
// ---------------------------------------------------------------------------

#define NTOK  25600      // 64*400 tokens

typedef unsigned long long u64;

// PP table: [13 chunks][96 chars][14 pieces][10 floats]  (chunk = 53760 B)
__device__ __align__(128) float g_pp[13 * 96 * 14 * 10];
// conv outputs: [NTOK][400]
__device__ __align__(128) float g_outs[(size_t)NTOK * 400];
// head intermediates: [NTOK][128]
__device__ __align__(128) float g_x1[(size_t)NTOK * 128];
__device__ __align__(128) float g_x2[(size_t)NTOK * 128];

// ---------------- packed fp32x2 + async helpers -----------------------------
__device__ __forceinline__ void ffma2(u64 &acc, u64 a, u64 b) {
    asm("fma.rn.f32x2 %0, %1, %2, %0;" : "+l"(acc) : "l"(a), "l"(b));
}
__device__ __forceinline__ u64 fadd2(u64 a, u64 b) {
    u64 r; asm("add.rn.f32x2 %0, %1, %2;" : "=l"(r) : "l"(a), "l"(b)); return r;
}
__device__ __forceinline__ void unpack2(u64 v, float &lo, float &hi) {
    asm("mov.b64 {%0, %1}, %2;" : "=f"(lo), "=f"(hi) : "l"(v));
}
__device__ __forceinline__ float hadd2(u64 v) {
    float lo, hi; unpack2(v, lo, hi); return lo + hi;
}
__device__ __forceinline__ float tanh_fast(float x) {
    float y;
    asm("tanh.approx.f32 %0, %1;" : "=f"(y) : "f"(x));
    return y;
}
__device__ __forceinline__ uint32_t smem_u32(const void* p) {
    return (uint32_t)__cvta_generic_to_shared(p);
}
__device__ __forceinline__ void cp16(uint32_t dst, const void* src) {
    asm volatile("cp.async.ca.shared.global [%0], [%1], 16;" :: "r"(dst), "l"(src));
}
__device__ __forceinline__ void cp_commit() {
    asm volatile("cp.async.commit_group;");
}
template<int N> __device__ __forceinline__ void cp_wait() {
    asm volatile("cp.async.wait_group %0;" :: "n"(N));
}
// ---- bulk-copy (UBLKCP) + mbarrier ----------------------------------------
__device__ __forceinline__ void mbar_init(uint32_t mbar, uint32_t cnt) {
    asm volatile("mbarrier.init.shared.b64 [%0], %1;" :: "r"(mbar), "r"(cnt) : "memory");
}
__device__ __forceinline__ void mbar_expect(uint32_t mbar, uint32_t tx) {
    asm volatile("mbarrier.arrive.expect_tx.shared.b64 _, [%0], %1;"
                 :: "r"(mbar), "r"(tx) : "memory");
}
__device__ __forceinline__ void bulk_g2s(uint32_t dst, const void* src,
                                         uint32_t bytes, uint32_t mbar) {
    asm volatile(
        "cp.async.bulk.shared::cluster.global.mbarrier::complete_tx::bytes "
        "[%0], [%1], %2, [%3];"
        :: "r"(dst), "l"(src), "r"(bytes), "r"(mbar) : "memory");
}
__device__ __forceinline__ void mbar_wait(uint32_t mbar, uint32_t parity) {
    asm volatile(
        "{\n\t.reg .pred P;\n"
        "WL_%=:\n\t"
        "mbarrier.try_wait.parity.acquire.cta.shared::cta.b64 P, [%0], %1, 0x989680;\n\t"
        "@P bra.uni WD_%=;\n\t"
        "bra.uni WL_%=;\n\t"
        "WD_%=:\n\t}"
        :: "r"(mbar), "r"(parity) : "memory");
}

// ---------------------------------------------------------------------------
// Kernel A: precompute PP (padded layout).  grid = (96, 14), 128 threads.
// ---------------------------------------------------------------------------
__global__ void pp_kernel(const float* __restrict__ cv,
                          const float* __restrict__ f2, const float* __restrict__ f3,
                          const float* __restrict__ f4, const float* __restrict__ f5)
{
    __shared__ float scv[64];
    const int c  = blockIdx.x;
    const int pg = blockIdx.y;
    const int j  = threadIdx.x;
    if (j < 64) scv[j] = __ldg(cv + c * 64 + j);
    __syncthreads();

    if (j < 104) {
        float s = 0.0f;
        if (j < 100) {
            const float* fp; int pl, RL;
            if (pg < 2)      { fp = f2; pl = pg;     RL = 2; }
            else if (pg < 5) { fp = f3; pl = pg - 2; RL = 3; }
            else if (pg < 9) { fp = f4; pl = pg - 5; RL = 4; }
            else             { fp = f5; pl = pg - 9; RL = 5; }
            const float4* fr = reinterpret_cast<const float4*>(fp + (j * RL + pl) * 64);
            #pragma unroll 4
            for (int q = 0; q < 16; q++) {
                const float4 fv = __ldg(fr + q);
                s += scv[4*q]   * fv.x + scv[4*q+1] * fv.y
                   + scv[4*q+2] * fv.z + scv[4*q+3] * fv.w;
            }
        }
        g_pp[(j >> 3) * 13440 + (c * 14 + pg) * 10 + (j & 7)] = s;
    }
}

// ---------------------------------------------------------------------------
// Kernel B: conv as table sums (R15/R12 exact).  grid = 400, 256 threads,
// 2 CTAs/SM; chunks bulk-copied (one UBLKCP each), double-buffered.
// ---------------------------------------------------------------------------
#define TB1  256
#define CHUNK_U64   6720                   // 96*14*5
#define CHUNK_BYTES 53760
#define SMEMB_BYTES (2 * CHUNK_BYTES)      // 107520 B

template<int W, int PB, int BOFF>
__device__ __forceinline__ void branch_sum(const u64* __restrict__ s_pp,
                                           const int (&bix)[16],
                                           float* __restrict__ orow,
                                           int g, int j2)
{
    constexpr int L = 17 - W;
    float m0 = -1e30f, m1 = -1e30f;
    #pragma unroll
    for (int l = 0; l < L; l++) {
        u64 a = s_pp[bix[l] + PB * 5];
        #pragma unroll
        for (int p = 1; p < W; p++)
            a = fadd2(a, s_pp[bix[l + p] + (PB + p) * 5]);
        float lo, hi; unpack2(a, lo, hi);
        m0 = fmaxf(m0, lo);
        m1 = fmaxf(m1, hi);
    }
    if (g < 12 || j2 < 2) {     // chunk 12: only filters 96..99 are real
        float2 r;
        r.x = tanh_fast(m0);
        r.y = tanh_fast(m1);
        *reinterpret_cast<float2*>(orow + BOFF + g * 8 + j2 * 2) = r;
    }
}

__global__ void __launch_bounds__(TB1, 2)
conv_sum_kernel(const int* __restrict__ idxs)
{
    extern __shared__ u64 s_pp2[];
    __shared__ __align__(8) u64 mb[2];
    u64* buf[2] = { s_pp2, s_pp2 + CHUNK_U64 };
    const uint32_t sb[2] = { smem_u32(buf[0]), smem_u32(buf[1]) };
    const uint32_t mbu[2] = { smem_u32(&mb[0]), smem_u32(&mb[1]) };

    const int tid = threadIdx.x;
    const int j2  = tid & 3;
    const int token = blockIdx.x * 64 + (tid >> 2);

    int bix[16];
    {
        const int4* ip4 = reinterpret_cast<const int4*>(idxs + token * 16);
        const int4 A = __ldg(ip4 + 0), B = __ldg(ip4 + 1);
        const int4 C = __ldg(ip4 + 2), D = __ldg(ip4 + 3);
        bix[ 0] = A.x * 70 + j2; bix[ 1] = A.y * 70 + j2;
        bix[ 2] = A.z * 70 + j2; bix[ 3] = A.w * 70 + j2;
        bix[ 4] = B.x * 70 + j2; bix[ 5] = B.y * 70 + j2;
        bix[ 6] = B.z * 70 + j2; bix[ 7] = B.w * 70 + j2;
        bix[ 8] = C.x * 70 + j2; bix[ 9] = C.y * 70 + j2;
        bix[10] = C.z * 70 + j2; bix[11] = C.w * 70 + j2;
        bix[12] = D.x * 70 + j2; bix[13] = D.y * 70 + j2;
        bix[14] = D.z * 70 + j2; bix[15] = D.w * 70 + j2;
    }

    float* orow = g_outs + (size_t)token * 400;

    if (tid == 0) { mbar_init(mbu[0], 1); mbar_init(mbu[1], 1); }
    __syncthreads();

    if (tid == 0) {
        mbar_expect(mbu[0], CHUNK_BYTES);
        bulk_g2s(sb[0], g_pp, CHUNK_BYTES, mbu[0]);
    }

    int ph0 = 0, ph1 = 0;
    #pragma unroll 1
    for (int g = 0; g < 13; g++) {
        if (g < 12 && tid == 0) {
            const int b = (g + 1) & 1;
            mbar_expect(mbu[b], CHUNK_BYTES);
            bulk_g2s(sb[b], g_pp + (g + 1) * 13440, CHUNK_BYTES, mbu[b]);
        }
        if (g & 1) { mbar_wait(mbu[1], ph1); ph1 ^= 1; }
        else       { mbar_wait(mbu[0], ph0); ph0 ^= 1; }

        const u64* sp = buf[g & 1];
        branch_sum<2, 0,   0>(sp, bix, orow, g, j2);
        branch_sum<3, 2, 100>(sp, bix, orow, g, j2);
        branch_sum<4, 5, 200>(sp, bix, orow, g, j2);
        branch_sum<5, 9, 300>(sp, bix, orow, g, j2);
        __syncthreads();
    }
}

// ---------------------------------------------------------------------------
// Kernel C1: projection, 16-token register blocking.  grid 400 (64 tok/CTA),
// 256 threads, 1 CTA/SM.  x panel (64x400, contiguous 102400B) bulk-copied
// once; w_proj streamed in 10 double-buffered cp16 chunks [128][40].
// thread = (c2 = tid&63 -> channels c2,c2+64; tg = tid>>6 -> 16 tokens).
// Per (kc,q): 2 weight LDS (8wf) + 16 x broadcasts (16wf) = 24wf vs
// 32 fma-cyc -> crossbar:fma = 0.75 (was 1.0); 32 independent acc chains.
// ---------------------------------------------------------------------------
#define PJ_XROW 400
#define PJ_XF   (64 * PJ_XROW)             // 25600 floats
#define PJ_WP   44
#define PJ_WF   (128 * PJ_WP)              // 5632 floats per buffer
#define PJ_SMEM ((PJ_XF + 2 * PJ_WF) * 4)  // 147456 B

__global__ void __launch_bounds__(256, 1)
proj_kernel(const float* __restrict__ wp, float* __restrict__ xout)
{
    extern __shared__ float sm[];
    __shared__ __align__(8) u64 pmb;
    float* s_x = sm;                       // [64][400]
    float* w0  = s_x + PJ_XF;              // [128][44]
    float* w1  = w0 + PJ_WF;
    const uint32_t xb  = smem_u32(s_x);
    const uint32_t wb[2] = { smem_u32(w0), smem_u32(w1) };
    const uint32_t pmbu = smem_u32(&pmb);
    float* const wf[2] = { w0, w1 };

    const int tid  = threadIdx.x;
    const int c2   = tid & 63;             // channels c2 and c2+64
    const int tg   = tid >> 6;             // token group 0..3 (16 tokens each)
    const int tok0 = blockIdx.x * 64;

    if (tid == 0) mbar_init(pmbu, 1);
    __syncthreads();
    if (tid == 0) {
        mbar_expect(pmbu, PJ_XF * 4);
        bulk_g2s(xb, g_outs + (size_t)tok0 * 400, PJ_XF * 4, pmbu);
    }

    auto stage_w = [&](int kc, uint32_t b) {
        #pragma unroll 1
        for (int i = tid; i < 1280; i += 256) {    // 128 rows x 10 quads
            const int r = i / 10, q = i - r * 10;
            cp16(b + (uint32_t)(r * PJ_WP + 4 * q) * 4u,
                 wp + r * 400 + kc * 40 + 4 * q);
        }
    };

    stage_w(0, wb[0]);
    cp_commit();

    u64 a0[16], a1[16];
    #pragma unroll
    for (int i = 0; i < 16; i++) { a0[i] = 0ull; a1[i] = 0ull; }

    mbar_wait(pmbu, 0);                    // x panel ready

    #pragma unroll 1
    for (int kc = 0; kc < 10; kc++) {
        if (kc < 9) { stage_w(kc + 1, wb[(kc + 1) & 1]); cp_commit(); cp_wait<1>(); }
        else        { cp_wait<0>(); }
        __syncthreads();
        const float* b = wf[kc & 1];
        #pragma unroll
        for (int q = 0; q < 10; q++) {
            const ulonglong2 wa = *reinterpret_cast<const ulonglong2*>(b + c2 * PJ_WP + 4 * q);
            const ulonglong2 wv = *reinterpret_cast<const ulonglong2*>(b + (c2 + 64) * PJ_WP + 4 * q);
            #pragma unroll
            for (int i = 0; i < 16; i++) {
                const ulonglong2 xv = *reinterpret_cast<const ulonglong2*>(
                    s_x + (tg * 16 + i) * PJ_XROW + kc * 40 + 4 * q);
                ffma2(a0[i], xv.x, wa.x); ffma2(a0[i], xv.y, wa.y);
                ffma2(a1[i], xv.x, wv.x); ffma2(a1[i], xv.y, wv.y);
            }
        }
        __syncthreads();                  // weight buffer kc&1 free
    }

    #pragma unroll
    for (int i = 0; i < 16; i++) {
        const int t = tok0 + tg * 16 + i;
        xout[(size_t)t * 128 + c2]      = hadd2(a0[i]);
        xout[(size_t)t * 128 + c2 + 64] = hadd2(a1[i]);
    }
}

// ---------------------------------------------------------------------------
// Kernel C2: one highway layer (R15 exact).  grid (148, 2), 256 threads,
// 2 CTAs/SM; channel-split resident weights; 16 tokens/thread.
// ---------------------------------------------------------------------------
#define HW_WF   (2 * 256 * 32)             // 16384 floats (65536 B)
#define HW_XU   33                         // float4 units per token row
#define HW_XF   (64 * HW_XU * 4)           // 8448 floats
#define HW_SMEM ((HW_WF + HW_XF) * 4)      // 99328 B

__global__ void __launch_bounds__(256, 2)
hwy_kernel(const float* __restrict__ tw, const float* __restrict__ tb,
           const float* __restrict__ gw, const float* __restrict__ gb,
           const float* __restrict__ xin, float* __restrict__ xout)
{
    extern __shared__ float sm[];
    float* sw = sm;                        // [2 mats][256 atoms][32 floats]
    float* xp = sw + HW_WF;                // [64][132]
    const uint32_t swb = smem_u32(sw);
    const uint32_t xpb = smem_u32(xp);

    const int tid = threadIdx.x;
    const int c   = tid & 63;
    const int tg  = tid >> 6;              // token group 0..3 (16 tokens each)
    const int h   = blockIdx.y;
    const int ch  = h * 64 + c;

    const float tbv = __ldg(tb + ch);
    const float gbv = __ldg(gb + ch);

    #pragma unroll 1
    for (int i = tid; i < 4096; i += 256) {
        const int m  = i >> 11;
        const int r  = (i >> 3) & 255;
        const int q  = i & 7;
        const int cc = r & 63;
        const int s  = r >> 6;
        const int dst = m * 2048 + r * 8 + (q ^ (cc & 7));
        const float* src = (m ? gw : tw) + (h * 64 + cc) * 128 + s * 32 + q * 4;
        cp16(swb + (uint32_t)dst * 16u, src);
    }
    cp_commit();

    const int qx = c & 7;

    #pragma unroll 1
    for (int b = blockIdx.x; b < 400; b += 148) {
        const int tok0 = b * 64;
        #pragma unroll 1
        for (int i = tid; i < 2048; i += 256) {
            const int t = i >> 5, u = i & 31;
            cp16(xpb + (uint32_t)(t * HW_XU + u) * 16u,
                 xin + (size_t)(tok0 + t) * 128 + u * 4);
        }
        cp_commit();
        cp_wait<0>();
        __syncthreads();

        u64 at[16], ag[16];
        #pragma unroll
        for (int i = 0; i < 16; i++) { at[i] = 0ull; ag[i] = 0ull; }

        #pragma unroll 1
        for (int s = 0; s < 4; s++) {
            #pragma unroll
            for (int q = 0; q < 8; q++) {
                const int qq = q ^ qx;
                const ulonglong2 wt = *reinterpret_cast<const ulonglong2*>(
                    sw + ((s * 64 + c) * 8 + qq) * 4);
                const ulonglong2 wg = *reinterpret_cast<const ulonglong2*>(
                    sw + 8192 + ((s * 64 + c) * 8 + qq) * 4);
                #pragma unroll
                for (int i = 0; i < 16; i++) {
                    const ulonglong2 xv = *reinterpret_cast<const ulonglong2*>(
                        xp + ((tg * 16 + i) * HW_XU + s * 8 + q) * 4);
                    ffma2(at[i], xv.x, wt.x); ffma2(at[i], xv.y, wt.y);
                    ffma2(ag[i], xv.x, wg.x); ffma2(ag[i], xv.y, wg.y);
                }
            }
        }

        #pragma unroll
        for (int i = 0; i < 16; i++) {
            const int t = tg * 16 + i;
            const float xo = xp[t * (HW_XU * 4) + ch];
            const float tv = fmaxf(hadd2(at[i]) + tbv, 0.0f);
            const float g  = 0.5f * tanh_fast(0.5f * (hadd2(ag[i]) + gbv)) + 0.5f;
            xout[(size_t)(tok0 + t) * 128 + ch] = g * tv + (1.0f - g) * xo;
        }

        __syncthreads();
    }
}

// ---------------------------------------------------------------------------
extern "C" void kernel_launch(void* const* d_in, const int* in_sizes, int n_in,
                              void* d_out, int out_size)
{
    const int*   idxs = (const int*)  d_in[0];
    const float* cv   = (const float*)d_in[1];
    const float* f2   = (const float*)d_in[2];
    const float* f3   = (const float*)d_in[3];
    const float* f4   = (const float*)d_in[4];
    const float* f5   = (const float*)d_in[5];
    const float* wp   = (const float*)d_in[6];
    const float* tw0  = (const float*)d_in[7];
    const float* tb0  = (const float*)d_in[8];
    const float* tw1  = (const float*)d_in[9];
    const float* tb1  = (const float*)d_in[10];
    const float* gw0  = (const float*)d_in[11];
    const float* gb0  = (const float*)d_in[12];
    const float* gw1  = (const float*)d_in[13];
    const float* gb1  = (const float*)d_in[14];
    float* out = (float*)d_out;

    static bool attr_done = false;
    if (!attr_done) {
        cudaFuncSetAttribute(conv_sum_kernel,
                             cudaFuncAttributeMaxDynamicSharedMemorySize, SMEMB_BYTES);
        cudaFuncSetAttribute(proj_kernel,
                             cudaFuncAttributeMaxDynamicSharedMemorySize, PJ_SMEM);
        cudaFuncSetAttribute(hwy_kernel,
                             cudaFuncAttributeMaxDynamicSharedMemorySize, HW_SMEM);
        attr_done = true;
    }

    float* x1; cudaGetSymbolAddress((void**)&x1, g_x1);
    float* x2; cudaGetSymbolAddress((void**)&x2, g_x2);

    pp_kernel<<<dim3(96, 14), 128>>>(cv, f2, f3, f4, f5);
    conv_sum_kernel<<<NTOK / 64, TB1, SMEMB_BYTES>>>(idxs);
    proj_kernel<<<NTOK / 64, 256, PJ_SMEM>>>(wp, x1);
    hwy_kernel<<<dim3(148, 2), 256, HW_SMEM>>>(tw0, tb0, gw0, gb0, x1, x2);
    hwy_kernel<<<dim3(148, 2), 256, HW_SMEM>>>(tw1, tb1, gw1, gb1, x2, out);
}